// round 6
// baseline (speedup 1.0000x reference)
#include <cuda_runtime.h>
#include <cstdint>
#define B_ 32
#define C_ 128
#define P_ 4096
#define PI_ 3.14159265358979323846f

__device__ float  g_xc[B_*C_*P_];
__device__ float  g_xl[B_*256*P_];
__device__ float  g_xo[B_*C_*P_];
__device__ float  g_cA[B_*256*P_];     // planar complex: rows 0-127 re, 128-255 im
__device__ float  g_we[C_*P_];
__device__ float  g_wn[4096];
__device__ float2 g_F64[4096];
__device__ float  g_WCf[256*128];      // fwd C-DFT weight [cos; -sin]
__device__ float  g_WCi[128*256];      // inv C-DFT weight [cos | -sin]/128
__device__ float  g_meanx[B_*C_];
__device__ int    g_expert[B_];

__global__ void k_consts(){
  int i=blockIdx.x*256+threadIdx.x;
  if(i<4096){
    int n=i>>6,h=i&63;
    float v=cospif((float)n*(h+0.5f)/64.f)*sqrtf(2.f/64.f);
    if(n==0)v*=0.70710678118654752f;
    g_wn[i]=v;
    float a=(float)((n*h)&63)/32.f;
    g_F64[i]=make_float2(cospif(a),-sinpif(a));
  }
  if(i<16384){
    int k=i>>7,j=i&127;
    float a=(float)((k*j)&127)/64.f;
    float c=cospif(a), s=-sinpif(a);
    g_WCf[k*128+j]=c;
    g_WCf[(128+k)*128+j]=s;
    g_WCi[j*256+k]=c*(1.f/128.f);
    g_WCi[j*256+128+k]=s*(1.f/128.f);
  }
}

__global__ __launch_bounds__(256) void k_we(const float* __restrict__ fe,
    const float* __restrict__ tw,const float* __restrict__ tb){
  __shared__ float sfe[128*33];
  int t=threadIdx.x,p0=blockIdx.x*32;
  for(int idx=t;idx<4096;idx+=256){int pl=idx>>7,c=idx&127;sfe[c*33+pl]=fe[(p0+pl)*128+c];}
  __syncthreads();
  int pl=t&31,cg=t>>5,p=p0+pl,h=p>>6,w=p&63;
  float s=(PI_*PI_/4096.f)*(float)(h*h+w*w);
  float acc[16];
  #pragma unroll
  for(int i=0;i<16;i++)acc[i]=0.f;
  for(int c2=0;c2<128;c2++){
    float f=sfe[c2*33+pl];
    #pragma unroll
    for(int i=0;i<16;i++)acc[i]+=f*__ldg(tw+(cg*16+i)*128+c2);
  }
  #pragma unroll
  for(int i=0;i<16;i++){
    int c=cg*16+i;
    float k=fmaxf(acc[i]+__ldg(tb+c),0.f);
    g_we[c*P_+p]=expf(-s*k);
  }
}

__global__ __launch_bounds__(256) void k_conv(const float* __restrict__ x,
    const float* __restrict__ wt,const float* __restrict__ bs){
  int b=blockIdx.z,c=blockIdx.y,p=blockIdx.x*256+threadIdx.x;
  int h=p>>6,w=p&63;
  const float* xp=x+(size_t)(b*C_+c)*P_;
  const float* wc=wt+c*9;
  float acc=__ldg(bs+c);
  #pragma unroll
  for(int dh=-1;dh<=1;dh++){
    int hh=h+dh; if(hh<0||hh>63)continue;
    #pragma unroll
    for(int dw=-1;dw<=1;dw++){
      int ww=w+dw; if(ww<0||ww>63)continue;
      acc+=xp[hh*64+ww]*__ldg(wc+(dh+1)*3+(dw+1));
    }
  }
  g_xc[(size_t)(b*C_+c)*P_+p]=acc;
}

// 128x128 block tile, 8x8 per thread. gate>=0: only batches with g_expert==gate.
__global__ __launch_bounds__(256,1) void k_gemm(
    const float* __restrict__ in, size_t inBS, int K,
    const float* __restrict__ W, const float* __restrict__ bias,
    float* __restrict__ out, size_t outBS, int gate){
  int b=blockIdx.z;
  if(gate>=0 && g_expert[b]!=gate) return;
  __shared__ float sA[16*132];
  __shared__ float sB[16*132];
  int t=threadIdx.x;
  int m0=blockIdx.y*128, p0=blockIdx.x*128;
  int tm=(t>>4)*8, tn=(t&15)*8;
  const float* X=in+(size_t)b*inBS;
  float acc[8][8]={};
  int nkt=K>>4;
  for(int kt=0;kt<nkt;kt++){
    {
      int m=t>>1, k8=(t&1)*8;
      const float* wp=W+(size_t)(m0+m)*K+kt*16+k8;
      float4 w0=*(const float4*)wp, w1=*(const float4*)(wp+4);
      sA[(k8+0)*132+m]=w0.x; sA[(k8+1)*132+m]=w0.y;
      sA[(k8+2)*132+m]=w0.z; sA[(k8+3)*132+m]=w0.w;
      sA[(k8+4)*132+m]=w1.x; sA[(k8+5)*132+m]=w1.y;
      sA[(k8+6)*132+m]=w1.z; sA[(k8+7)*132+m]=w1.w;
    }
    {
      int k=t>>4, px=(t&15)*8;
      const float* xp=X+(size_t)(kt*16+k)*P_+p0+px;
      *(float4*)&sB[k*132+px]=*(const float4*)xp;
      *(float4*)&sB[k*132+px+4]=*(const float4*)(xp+4);
    }
    __syncthreads();
    #pragma unroll
    for(int k=0;k<16;k++){
      float4 a0=*(const float4*)&sA[k*132+tm];
      float4 a1=*(const float4*)&sA[k*132+tm+4];
      float4 b0=*(const float4*)&sB[k*132+tn];
      float4 b1=*(const float4*)&sB[k*132+tn+4];
      float av[8]={a0.x,a0.y,a0.z,a0.w,a1.x,a1.y,a1.z,a1.w};
      float bv[8]={b0.x,b0.y,b0.z,b0.w,b1.x,b1.y,b1.z,b1.w};
      #pragma unroll
      for(int i=0;i<8;i++)
        #pragma unroll
        for(int j=0;j<8;j++) acc[i][j]+=av[i]*bv[j];
    }
    __syncthreads();
  }
  #pragma unroll
  for(int i=0;i<8;i++){
    int m=m0+tm+i;
    float bb=bias?__ldg(bias+m):0.f;
    float* op=out+(size_t)b*outBS+(size_t)m*P_+p0+tn;
    *(float4*)op    =make_float4(acc[i][0]+bb,acc[i][1]+bb,acc[i][2]+bb,acc[i][3]+bb);
    *(float4*)(op+4)=make_float4(acc[i][4]+bb,acc[i][5]+bb,acc[i][6]+bb,acc[i][7]+bb);
  }
}

__global__ void k_mean(){
  __shared__ float r[128];
  int c=blockIdx.x,b=blockIdx.y;
  const float* p=g_xl+(size_t)(b*256+c)*P_;
  float s=0.f;
  for(int i=threadIdx.x;i<P_;i+=128)s+=p[i];
  r[threadIdx.x]=s;__syncthreads();
  for(int st=64;st>0;st>>=1){if(threadIdx.x<st)r[threadIdx.x]+=r[threadIdx.x+st];__syncthreads();}
  if(threadIdx.x==0)g_meanx[b*128+c]=r[0]*(1.f/P_);
}

__global__ __launch_bounds__(256) void k_router(const float* p1w,const float* p1b,
    const float* g1,const float* b1,const float* p2w,const float* p2b,
    const float* g2,const float* b2,const float* p3w,const float* p3b,const float* gum){
  __shared__ float h1[8192],h2[1024];
  int t=threadIdx.x;
  for(int idx=t;idx<8192;idx+=256){
    int b=idx>>8,o=idx&255;float a=p1b[o];
    for(int c=0;c<128;c++)a+=g_meanx[b*128+c]*p1w[o*128+c];
    h1[idx]=a>0.f?a:0.1f*a;
  }
  __syncthreads();
  {int o=t;float s=0,s2=0;
   for(int b=0;b<32;b++){float v=h1[b*256+o];s+=v;s2+=v*v;}
   float mu=s/32.f,rs=rsqrtf(fmaxf(s2/32.f-mu*mu,0.f)+1e-5f);
   for(int b=0;b<32;b++)h1[b*256+o]=(h1[b*256+o]-mu)*rs*g1[o]+b1[o];}
  __syncthreads();
  for(int idx=t;idx<1024;idx+=256){
    int b=idx>>5,j=idx&31;float a=p2b[j];
    for(int o=0;o<256;o++)a+=h1[b*256+o]*p2w[j*256+o];
    h2[idx]=a>0.f?a:0.1f*a;
  }
  __syncthreads();
  if(t<32){int j=t;float s=0,s2=0;
   for(int b=0;b<32;b++){float v=h2[b*32+j];s+=v;s2+=v*v;}
   float mu=s/32.f,rs=rsqrtf(fmaxf(s2/32.f-mu*mu,0.f)+1e-5f);
   for(int b=0;b<32;b++)h2[b*32+j]=(h2[b*32+j]-mu)*rs*g2[j]+b2[j];}
  __syncthreads();
  if(t<32){int b=t;float best=-1e30f;int bi=0;
   for(int r=0;r<3;r++){
     float l=p3b[r]+gum[b*3+r];
     for(int j=0;j<32;j++)l+=h2[b*32+j]*p3w[r*32+j];
     if(l>best){best=l;bi=r;}
   }
   g_expert[b]=bi;}
}

__device__ __forceinline__ void rmm4(float* sP,const float* M,int tr){
  int t=threadIdx.x; int j0=(t&15)*4, r0=(t>>4)*4;
  float acc[4][4]={};
  for(int k=0;k<64;k++){
    float xv[4];
    #pragma unroll
    for(int jj=0;jj<4;jj++) xv[jj]=sP[k*65+j0+jj];
    #pragma unroll
    for(int rr=0;rr<4;rr++){
      float m=tr?M[k*64+r0+rr]:M[(r0+rr)*64+k];
      #pragma unroll
      for(int jj=0;jj<4;jj++) acc[rr][jj]+=m*xv[jj];
    }
  }
  __syncthreads();
  #pragma unroll
  for(int rr=0;rr<4;rr++)
    #pragma unroll
    for(int jj=0;jj<4;jj++) sP[(j0+jj)*65+r0+rr]=acc[rr][jj];
  __syncthreads();
}

__global__ __launch_bounds__(256) void k_dct(){
  int c=blockIdx.x,b=blockIdx.y;
  if(g_expert[b]!=0)return;
  __shared__ float sP[64*65]; __shared__ float sM[4096];
  int t=threadIdx.x;
  const float* src=g_xl+(size_t)(b*256+c)*P_;
  for(int idx=t;idx<4096;idx+=256){sM[idx]=g_wn[idx];sP[(idx>>6)*65+(idx&63)]=src[idx];}
  __syncthreads();
  rmm4(sP,sM,0);
  rmm4(sP,sM,0);
  for(int idx=t;idx<4096;idx+=256)sP[(idx>>6)*65+(idx&63)]*=__ldg(&g_we[c*P_+idx]);
  __syncthreads();
  rmm4(sP,sM,1);
  rmm4(sP,sM,1);
  float* dst=g_xo+(size_t)(b*C_+c)*P_;
  for(int idx=t;idx<4096;idx+=256)dst[idx]=sP[(idx>>6)*65+(idx&63)];
}

// ---------------- radix-8 FFT machinery ----------------
__device__ __forceinline__ float2 cmul(float2 a,float2 b){return make_float2(a.x*b.x-a.y*b.y,a.x*b.y+a.y*b.x);}
__device__ __forceinline__ float2 cmulc(float2 a,float2 b){return make_float2(a.x*b.x+a.y*b.y,a.y*b.x-a.x*b.y);}
__device__ __forceinline__ float2 cadd(float2 a,float2 b){return make_float2(a.x+b.x,a.y+b.y);}
__device__ __forceinline__ float2 csub(float2 a,float2 b){return make_float2(a.x-b.x,a.y-b.y);}

__device__ __forceinline__ void fft8(float2* a,float s){
  const float c8=0.70710678118654752f;
  float2 w1=make_float2(c8,s*c8),w2=make_float2(0.f,s),w3=make_float2(-c8,s*c8),t;
  t=csub(a[0],a[4]);a[0]=cadd(a[0],a[4]);a[4]=t;
  t=csub(a[1],a[5]);a[1]=cadd(a[1],a[5]);a[5]=cmul(t,w1);
  t=csub(a[2],a[6]);a[2]=cadd(a[2],a[6]);a[6]=cmul(t,w2);
  t=csub(a[3],a[7]);a[3]=cadd(a[3],a[7]);a[7]=cmul(t,w3);
  t=csub(a[0],a[2]);a[0]=cadd(a[0],a[2]);a[2]=t;
  t=csub(a[1],a[3]);a[1]=cadd(a[1],a[3]);a[3]=cmul(t,w2);
  t=csub(a[4],a[6]);a[4]=cadd(a[4],a[6]);a[6]=t;
  t=csub(a[5],a[7]);a[5]=cadd(a[5],a[7]);a[7]=cmul(t,w2);
  t=csub(a[0],a[1]);a[0]=cadd(a[0],a[1]);a[1]=t;
  t=csub(a[2],a[3]);a[2]=cadd(a[2],a[3]);a[3]=t;
  t=csub(a[4],a[5]);a[4]=cadd(a[4],a[5]);a[5]=t;
  t=csub(a[6],a[7]);a[6]=cadd(a[6],a[7]);a[7]=t;
  t=a[1];a[1]=a[4];a[4]=t;
  t=a[3];a[3]=a[6];a[6]=t;
}

__device__ void fft64_dir(float2* sP,int es,int vs,float sgn,bool inverse){
  int t=threadIdx.x,v=t&63,sl=t>>6;
  #pragma unroll
  for(int gi=0;gi<2;gi++){
    int g=sl+gi*4;
    float2 a[8];
    if(!inverse){
      #pragma unroll
      for(int n1=0;n1<8;n1++)a[n1]=sP[(8*n1+g)*es+v*vs];
      fft8(a,sgn);
      #pragma unroll
      for(int k1=1;k1<8;k1++)a[k1]=cmul(a[k1],__ldg(&g_F64[g*64+k1]));
      #pragma unroll
      for(int k1=0;k1<8;k1++)sP[(8*k1+g)*es+v*vs]=a[k1];
    }else{
      #pragma unroll
      for(int k2=0;k2<8;k2++)a[k2]=sP[(8*g+k2)*es+v*vs];
      fft8(a,sgn);
      #pragma unroll
      for(int n2=1;n2<8;n2++)a[n2]=cmulc(a[n2],__ldg(&g_F64[n2*64+g]));
      #pragma unroll
      for(int n2=0;n2<8;n2++)sP[(8*g+n2)*es+v*vs]=a[n2];
    }
  }
  __syncthreads();
  #pragma unroll
  for(int gi=0;gi<2;gi++){
    int g=sl+gi*4;
    float2 a[8];
    if(!inverse){
      #pragma unroll
      for(int n2=0;n2<8;n2++)a[n2]=sP[(8*g+n2)*es+v*vs];
      fft8(a,sgn);
      #pragma unroll
      for(int k2=0;k2<8;k2++)sP[(8*g+k2)*es+v*vs]=a[k2];
    }else{
      #pragma unroll
      for(int k1=0;k1<8;k1++)a[k1]=sP[(8*k1+g)*es+v*vs];
      fft8(a,sgn);
      #pragma unroll
      for(int n1=0;n1<8;n1++)sP[(8*n1+g)*es+v*vs]=a[n1];
    }
  }
  __syncthreads();
}

// fused plane filter on planar complex
__global__ __launch_bounds__(256) void k_pfft(){
  int c=blockIdx.x,b=blockIdx.y;
  if(g_expert[b]!=1)return;
  __shared__ float2 sP[64*65];
  int t=threadIdx.x;
  float* re=g_cA+(size_t)(b*256+c)*P_;
  float* im=g_cA+(size_t)(b*256+128+c)*P_;
  for(int idx=t;idx<4096;idx+=256)
    sP[(idx>>6)*65+(idx&63)]=make_float2(re[idx],im[idx]);
  __syncthreads();
  fft64_dir(sP,65,1,-1.f,false);
  fft64_dir(sP,1,65,-1.f,false);
  for(int idx=t;idx<4096;idx+=256){
    int ph=idx>>6,pw=idx&63;
    int f=(((ph&7)<<3)|(ph>>3))*64+(((pw&7)<<3)|(pw>>3));
    float w=__ldg(&g_we[c*P_+f])*(1.f/4096.f);
    float2 v=sP[ph*65+pw];
    sP[ph*65+pw]=make_float2(v.x*w,v.y*w);
  }
  __syncthreads();
  fft64_dir(sP,1,65,1.f,true);
  fft64_dir(sP,65,1,1.f,true);
  for(int idx=t;idx<4096;idx+=256){
    float2 v=sP[(idx>>6)*65+(idx&63)];
    re[idx]=v.x; im[idx]=v.y;
  }
}

__global__ __launch_bounds__(256) void k_haar(){
  int b=blockIdx.y;
  if(g_expert[b]!=2)return;
  int gid=blockIdx.x*256+threadIdx.x;
  int cp=gid>>11,q=gid&2047,h=q>>5,wp=q&31;
  size_t i0=(size_t)(b*256+2*cp)*P_+h*64+2*wp;
  float2 t0=*(const float2*)(g_xl+i0);
  float2 t1=*(const float2*)(g_xl+i0+P_);
  float sab=t0.x+t0.y,dab=t0.x-t0.y,scd=t1.x+t1.y,dcd=t1.x-t1.y;
  int pa=h*64+wp,pd=h*64+32+wp;
  float u00=(sab+scd)*0.25f*__ldg(&g_we[cp*P_+pa]);
  float u10=(sab-scd)*0.25f*__ldg(&g_we[(64+cp)*P_+pa]);
  float u01=(dab+dcd)*0.25f*__ldg(&g_we[cp*P_+pd]);
  float u11=(dab-dcd)*0.25f*__ldg(&g_we[(64+cp)*P_+pd]);
  float r0=u00+u01,r1=u00-u01,s0=u10+u11,s1=u10-u11;
  size_t o0=(size_t)(b*C_+2*cp)*P_+h*64+2*wp;
  *(float2*)(g_xo+o0)=make_float2(r0+s0,r1+s1);
  *(float2*)(g_xo+o0+P_)=make_float2(r0-s0,r1-s1);
}

__global__ __launch_bounds__(256) void k_lng(const float* __restrict__ og,
    const float* __restrict__ ob){
  __shared__ float sxo[128*65];
  __shared__ float part[256],part2[256];
  __shared__ float smu[64],srs[64];
  int b=blockIdx.y,p0=blockIdx.x*64,t=threadIdx.x;
  for(int idx=t;idx<8192;idx+=256){
    int c=idx>>6,p=idx&63;
    sxo[c*65+p]=g_xo[(size_t)(b*C_+c)*P_+p0+p];
  }
  __syncthreads();
  {
    int p=t&63,q=t>>6;
    float s=0.f,s2=0.f;
    for(int c=q*32;c<q*32+32;c++){float v=sxo[c*65+p];s+=v;s2+=v*v;}
    part[t]=s;part2[t]=s2;
  }
  __syncthreads();
  if(t<64){
    float S=part[t]+part[t+64]+part[t+128]+part[t+192];
    float S2=part2[t]+part2[t+64]+part2[t+128]+part2[t+192];
    float m=S*(1.f/128.f);
    smu[t]=m;
    srs[t]=rsqrtf(fmaxf(S2*(1.f/128.f)-m*m,0.f)+1e-5f);
  }
  __syncthreads();
  for(int idx=t;idx<8192;idx+=256){
    int c=idx>>6,p=idx&63;
    float z=g_xl[(size_t)(b*256+128+c)*P_+p0+p];
    float sil=z/(1.f+expf(-z));
    g_xc[(size_t)(b*C_+c)*P_+p0+p]=
      ((sxo[c*65+p]-smu[p])*srs[p]*__ldg(og+c)+__ldg(ob+c))*sil;
  }
}

extern "C" void kernel_launch(void* const* d_in,const int* in_sizes,int n_in,
                              void* d_out,int out_size){
  const float* x=(const float*)d_in[0];
  const float* fe=(const float*)d_in[1];
  const float* dww=(const float*)d_in[2];
  const float* dwb=(const float*)d_in[3];
  const float* lw=(const float*)d_in[4];
  const float* lb=(const float*)d_in[5];
  const float* p1w=(const float*)d_in[6];
  const float* p1b=(const float*)d_in[7];
  const float* g1=(const float*)d_in[8];
  const float* b1=(const float*)d_in[9];
  const float* p2w=(const float*)d_in[10];
  const float* p2b=(const float*)d_in[11];
  const float* g2=(const float*)d_in[12];
  const float* b2=(const float*)d_in[13];
  const float* p3w=(const float*)d_in[14];
  const float* p3b=(const float*)d_in[15];
  const float* tw=(const float*)d_in[16];
  const float* tb=(const float*)d_in[17];
  const float* og=(const float*)d_in[18];
  const float* ob=(const float*)d_in[19];
  const float* olw=(const float*)d_in[20];
  const float* olb=(const float*)d_in[21];
  const float* gum=(const float*)d_in[22];
  float* out=(float*)d_out;
  float *gxc,*gxl,*gxo,*gca,*gwcf,*gwci;
  cudaGetSymbolAddress((void**)&gxc,g_xc);
  cudaGetSymbolAddress((void**)&gxl,g_xl);
  cudaGetSymbolAddress((void**)&gxo,g_xo);
  cudaGetSymbolAddress((void**)&gca,g_cA);
  cudaGetSymbolAddress((void**)&gwcf,g_WCf);
  cudaGetSymbolAddress((void**)&gwci,g_WCi);

  k_consts<<<64,256>>>();
  k_we<<<128,256>>>(fe,tw,tb);
  k_conv<<<dim3(16,128,32),256>>>(x,dww,dwb);
  k_gemm<<<dim3(32,2,32),256>>>(gxc,(size_t)128*P_,128,lw,lb,gxl,(size_t)256*P_,-1);
  k_mean<<<dim3(128,32),128>>>();
  k_router<<<1,256>>>(p1w,p1b,g1,b1,p2w,p2b,g2,b2,p3w,p3b,gum);
  k_dct<<<dim3(128,32),256>>>();
  k_gemm<<<dim3(32,2,32),256>>>(gxl,(size_t)256*P_,128,gwcf,(const float*)0,gca,(size_t)256*P_,1);
  k_pfft<<<dim3(128,32),256>>>();
  k_gemm<<<dim3(32,1,32),256>>>(gca,(size_t)256*P_,256,gwci,(const float*)0,gxo,(size_t)128*P_,1);
  k_haar<<<dim3(512,32),256>>>();
  k_lng<<<dim3(64,32),256>>>(og,ob);
  k_gemm<<<dim3(32,1,32),256>>>(gxc,(size_t)128*P_,128,olw,olb,out,(size_t)128*P_,-1);
}

// round 7
// speedup vs baseline: 1.5243x; 1.5243x over previous
#include <cuda_runtime.h>
#include <cstdint>
#define B_ 32
#define C_ 128
#define P_ 4096
#define PI_ 3.14159265358979323846f

__device__ float  g_xc[B_*C_*P_];
__device__ float  g_xl[B_*256*P_];
__device__ float  g_xo[B_*C_*P_];
__device__ float  g_cA[B_*256*P_];     // planar complex: rows 0-127 re, 128-255 im
__device__ float  g_we[C_*P_];
__device__ float  g_wn[4096];
__device__ float2 g_F64[4096];
__device__ float  g_WCf[256*128];
__device__ float  g_WCi[128*256];
__device__ float  g_meanx[B_*C_];
__device__ int    g_expert[B_];

__global__ void k_consts(){
  int i=blockIdx.x*256+threadIdx.x;
  if(i<4096){
    int n=i>>6,h=i&63;
    float v=cospif((float)n*(h+0.5f)/64.f)*sqrtf(2.f/64.f);
    if(n==0)v*=0.70710678118654752f;
    g_wn[i]=v;
    float a=(float)((n*h)&63)/32.f;
    g_F64[i]=make_float2(cospif(a),-sinpif(a));
  }
  if(i<16384){
    int k=i>>7,j=i&127;
    float a=(float)((k*j)&127)/64.f;
    float c=cospif(a), s=-sinpif(a);
    g_WCf[k*128+j]=c;
    g_WCf[(128+k)*128+j]=s;
    g_WCi[j*256+k]=c*(1.f/128.f);
    g_WCi[j*256+128+k]=s*(1.f/128.f);
  }
}

__global__ __launch_bounds__(256) void k_we(const float* __restrict__ fe,
    const float* __restrict__ tw,const float* __restrict__ tb){
  __shared__ float sfe[128*33];
  int t=threadIdx.x,p0=blockIdx.x*32;
  for(int idx=t;idx<4096;idx+=256){int pl=idx>>7,c=idx&127;sfe[c*33+pl]=fe[(p0+pl)*128+c];}
  __syncthreads();
  int pl=t&31,cg=t>>5,p=p0+pl,h=p>>6,w=p&63;
  float s=(PI_*PI_/4096.f)*(float)(h*h+w*w);
  float acc[16];
  #pragma unroll
  for(int i=0;i<16;i++)acc[i]=0.f;
  for(int c2=0;c2<128;c2++){
    float f=sfe[c2*33+pl];
    #pragma unroll
    for(int i=0;i<16;i++)acc[i]+=f*__ldg(tw+(cg*16+i)*128+c2);
  }
  #pragma unroll
  for(int i=0;i<16;i++){
    int c=cg*16+i;
    float k=fmaxf(acc[i]+__ldg(tb+c),0.f);
    g_we[c*P_+p]=expf(-s*k);
  }
}

__global__ __launch_bounds__(256) void k_conv(const float* __restrict__ x,
    const float* __restrict__ wt,const float* __restrict__ bs){
  int b=blockIdx.z,c=blockIdx.y,p=blockIdx.x*256+threadIdx.x;
  int h=p>>6,w=p&63;
  const float* xp=x+(size_t)(b*C_+c)*P_;
  const float* wc=wt+c*9;
  float acc=__ldg(bs+c);
  #pragma unroll
  for(int dh=-1;dh<=1;dh++){
    int hh=h+dh; if(hh<0||hh>63)continue;
    #pragma unroll
    for(int dw=-1;dw<=1;dw++){
      int ww=w+dw; if(ww<0||ww>63)continue;
      acc+=xp[hh*64+ww]*__ldg(wc+(dh+1)*3+(dw+1));
    }
  }
  g_xc[(size_t)(b*C_+c)*P_+p]=acc;
}

// R4-proven gemm: 64x64 tile, 4x4/thread. gate>=0 -> only batches with that expert.
__global__ __launch_bounds__(256) void k_gemm(const float* __restrict__ in, size_t inBS, int K,
    const float* __restrict__ W,const float* __restrict__ bias,
    float* __restrict__ out, size_t outBS, int gate){
  int b=blockIdx.z;
  if(gate>=0 && g_expert[b]!=gate)return;
  __shared__ float sA[16*65]; __shared__ float4 sB[256];
  int m0=blockIdx.y*64,p0=blockIdx.x*64,t=threadIdx.x;
  int tx=t&15,ty=t>>4;
  const float* X=in+(size_t)b*inBS;
  float acc[4][4]={};
  int nkt=K>>4;
  for(int kt=0;kt<nkt;kt++){
    #pragma unroll
    for(int i=0;i<4;i++){int idx=t+i*256;sA[(idx&15)*65+(idx>>4)]=W[(size_t)(m0+(idx>>4))*K+kt*16+(idx&15)];}
    sB[t]=*(const float4*)(X+(size_t)(kt*16+(t>>4))*P_+p0+(t&15)*4);
    __syncthreads();
    #pragma unroll
    for(int k=0;k<16;k++){
      float4 bv=sB[k*16+tx];
      #pragma unroll
      for(int i=0;i<4;i++){
        float a=sA[k*65+ty*4+i];
        acc[i][0]+=a*bv.x;acc[i][1]+=a*bv.y;acc[i][2]+=a*bv.z;acc[i][3]+=a*bv.w;
      }
    }
    __syncthreads();
  }
  #pragma unroll
  for(int i=0;i<4;i++){
    int m=m0+ty*4+i;
    float bb=bias?__ldg(bias+m):0.f;
    *(float4*)(out+(size_t)b*outBS+(size_t)m*P_+p0+tx*4)=
      make_float4(acc[i][0]+bb,acc[i][1]+bb,acc[i][2]+bb,acc[i][3]+bb);
  }
}

__global__ void k_mean(){
  __shared__ float r[128];
  int c=blockIdx.x,b=blockIdx.y;
  const float* p=g_xl+(size_t)(b*256+c)*P_;
  float s=0.f;
  for(int i=threadIdx.x;i<P_;i+=128)s+=p[i];
  r[threadIdx.x]=s;__syncthreads();
  for(int st=64;st>0;st>>=1){if(threadIdx.x<st)r[threadIdx.x]+=r[threadIdx.x+st];__syncthreads();}
  if(threadIdx.x==0)g_meanx[b*128+c]=r[0]*(1.f/P_);
}

__global__ __launch_bounds__(256) void k_router(const float* p1w,const float* p1b,
    const float* g1,const float* b1,const float* p2w,const float* p2b,
    const float* g2,const float* b2,const float* p3w,const float* p3b,const float* gum){
  __shared__ float h1[8192],h2[1024];
  int t=threadIdx.x;
  for(int idx=t;idx<8192;idx+=256){
    int b=idx>>8,o=idx&255;float a=p1b[o];
    for(int c=0;c<128;c++)a+=g_meanx[b*128+c]*p1w[o*128+c];
    h1[idx]=a>0.f?a:0.1f*a;
  }
  __syncthreads();
  {int o=t;float s=0,s2=0;
   for(int b=0;b<32;b++){float v=h1[b*256+o];s+=v;s2+=v*v;}
   float mu=s/32.f,rs=rsqrtf(fmaxf(s2/32.f-mu*mu,0.f)+1e-5f);
   for(int b=0;b<32;b++)h1[b*256+o]=(h1[b*256+o]-mu)*rs*g1[o]+b1[o];}
  __syncthreads();
  for(int idx=t;idx<1024;idx+=256){
    int b=idx>>5,j=idx&31;float a=p2b[j];
    for(int o=0;o<256;o++)a+=h1[b*256+o]*p2w[j*256+o];
    h2[idx]=a>0.f?a:0.1f*a;
  }
  __syncthreads();
  if(t<32){int j=t;float s=0,s2=0;
   for(int b=0;b<32;b++){float v=h2[b*32+j];s+=v;s2+=v*v;}
   float mu=s/32.f,rs=rsqrtf(fmaxf(s2/32.f-mu*mu,0.f)+1e-5f);
   for(int b=0;b<32;b++)h2[b*32+j]=(h2[b*32+j]-mu)*rs*g2[j]+b2[j];}
  __syncthreads();
  if(t<32){int b=t;float best=-1e30f;int bi=0;
   for(int r=0;r<3;r++){
     float l=p3b[r]+gum[b*3+r];
     for(int j=0;j<32;j++)l+=h2[b*32+j]*p3w[r*32+j];
     if(l>best){best=l;bi=r;}
   }
   g_expert[b]=bi;}
}

__device__ __forceinline__ void rmm4(float* sP,const float* M,int tr){
  int t=threadIdx.x; int j0=(t&15)*4, r0=(t>>4)*4;
  float acc[4][4]={};
  for(int k=0;k<64;k++){
    float xv[4];
    #pragma unroll
    for(int jj=0;jj<4;jj++) xv[jj]=sP[k*65+j0+jj];
    #pragma unroll
    for(int rr=0;rr<4;rr++){
      float m=tr?M[k*64+r0+rr]:M[(r0+rr)*64+k];
      #pragma unroll
      for(int jj=0;jj<4;jj++) acc[rr][jj]+=m*xv[jj];
    }
  }
  __syncthreads();
  #pragma unroll
  for(int rr=0;rr<4;rr++)
    #pragma unroll
    for(int jj=0;jj<4;jj++) sP[(j0+jj)*65+r0+rr]=acc[rr][jj];
  __syncthreads();
}

__global__ __launch_bounds__(256) void k_dct(){
  int c=blockIdx.x,b=blockIdx.y;
  if(g_expert[b]!=0)return;
  __shared__ float sP[64*65]; __shared__ float sM[4096];
  int t=threadIdx.x;
  const float* src=g_xl+(size_t)(b*256+c)*P_;
  for(int idx=t;idx<4096;idx+=256){sM[idx]=g_wn[idx];sP[(idx>>6)*65+(idx&63)]=src[idx];}
  __syncthreads();
  rmm4(sP,sM,0);
  rmm4(sP,sM,0);
  for(int idx=t;idx<4096;idx+=256)sP[(idx>>6)*65+(idx&63)]*=__ldg(&g_we[c*P_+idx]);
  __syncthreads();
  rmm4(sP,sM,1);
  rmm4(sP,sM,1);
  float* dst=g_xo+(size_t)(b*C_+c)*P_;
  for(int idx=t;idx<4096;idx+=256)dst[idx]=sP[(idx>>6)*65+(idx&63)];
}

// ---------------- radix-8 FFT ----------------
__device__ __forceinline__ float2 cmul(float2 a,float2 b){return make_float2(a.x*b.x-a.y*b.y,a.x*b.y+a.y*b.x);}
__device__ __forceinline__ float2 cmulc(float2 a,float2 b){return make_float2(a.x*b.x+a.y*b.y,a.y*b.x-a.x*b.y);}
__device__ __forceinline__ float2 cadd(float2 a,float2 b){return make_float2(a.x+b.x,a.y+b.y);}
__device__ __forceinline__ float2 csub(float2 a,float2 b){return make_float2(a.x-b.x,a.y-b.y);}

__device__ __forceinline__ void fft8(float2* a,float s){
  const float c8=0.70710678118654752f;
  float2 w1=make_float2(c8,s*c8),w2=make_float2(0.f,s),w3=make_float2(-c8,s*c8),t;
  t=csub(a[0],a[4]);a[0]=cadd(a[0],a[4]);a[4]=t;
  t=csub(a[1],a[5]);a[1]=cadd(a[1],a[5]);a[5]=cmul(t,w1);
  t=csub(a[2],a[6]);a[2]=cadd(a[2],a[6]);a[6]=cmul(t,w2);
  t=csub(a[3],a[7]);a[3]=cadd(a[3],a[7]);a[7]=cmul(t,w3);
  t=csub(a[0],a[2]);a[0]=cadd(a[0],a[2]);a[2]=t;
  t=csub(a[1],a[3]);a[1]=cadd(a[1],a[3]);a[3]=cmul(t,w2);
  t=csub(a[4],a[6]);a[4]=cadd(a[4],a[6]);a[6]=t;
  t=csub(a[5],a[7]);a[5]=cadd(a[5],a[7]);a[7]=cmul(t,w2);
  t=csub(a[0],a[1]);a[0]=cadd(a[0],a[1]);a[1]=t;
  t=csub(a[2],a[3]);a[2]=cadd(a[2],a[3]);a[3]=t;
  t=csub(a[4],a[5]);a[4]=cadd(a[4],a[5]);a[5]=t;
  t=csub(a[6],a[7]);a[6]=cadd(a[6],a[7]);a[7]=t;
  t=a[1];a[1]=a[4];a[4]=t;
  t=a[3];a[3]=a[6];a[6]=t;
}

__device__ void fft64_dir(float2* sP,int es,int vs,float sgn,bool inverse){
  int t=threadIdx.x,v=t&63,sl=t>>6;
  #pragma unroll
  for(int gi=0;gi<2;gi++){
    int g=sl+gi*4;
    float2 a[8];
    if(!inverse){
      #pragma unroll
      for(int n1=0;n1<8;n1++)a[n1]=sP[(8*n1+g)*es+v*vs];
      fft8(a,sgn);
      #pragma unroll
      for(int k1=1;k1<8;k1++)a[k1]=cmul(a[k1],__ldg(&g_F64[g*64+k1]));
      #pragma unroll
      for(int k1=0;k1<8;k1++)sP[(8*k1+g)*es+v*vs]=a[k1];
    }else{
      #pragma unroll
      for(int k2=0;k2<8;k2++)a[k2]=sP[(8*g+k2)*es+v*vs];
      fft8(a,sgn);
      #pragma unroll
      for(int n2=1;n2<8;n2++)a[n2]=cmulc(a[n2],__ldg(&g_F64[n2*64+g]));
      #pragma unroll
      for(int n2=0;n2<8;n2++)sP[(8*g+n2)*es+v*vs]=a[n2];
    }
  }
  __syncthreads();
  #pragma unroll
  for(int gi=0;gi<2;gi++){
    int g=sl+gi*4;
    float2 a[8];
    if(!inverse){
      #pragma unroll
      for(int n2=0;n2<8;n2++)a[n2]=sP[(8*g+n2)*es+v*vs];
      fft8(a,sgn);
      #pragma unroll
      for(int k2=0;k2<8;k2++)sP[(8*g+k2)*es+v*vs]=a[k2];
    }else{
      #pragma unroll
      for(int k1=0;k1<8;k1++)a[k1]=sP[(8*k1+g)*es+v*vs];
      fft8(a,sgn);
      #pragma unroll
      for(int n1=0;n1<8;n1++)sP[(8*n1+g)*es+v*vs]=a[n1];
    }
  }
  __syncthreads();
}

__global__ __launch_bounds__(256) void k_pfft(){
  int c=blockIdx.x,b=blockIdx.y;
  if(g_expert[b]!=1)return;
  __shared__ float2 sP[64*65];
  int t=threadIdx.x;
  float* re=g_cA+(size_t)(b*256+c)*P_;
  float* im=g_cA+(size_t)(b*256+128+c)*P_;
  for(int idx=t;idx<4096;idx+=256)
    sP[(idx>>6)*65+(idx&63)]=make_float2(re[idx],im[idx]);
  __syncthreads();
  fft64_dir(sP,65,1,-1.f,false);
  fft64_dir(sP,1,65,-1.f,false);
  for(int idx=t;idx<4096;idx+=256){
    int ph=idx>>6,pw=idx&63;
    int f=(((ph&7)<<3)|(ph>>3))*64+(((pw&7)<<3)|(pw>>3));
    float w=__ldg(&g_we[c*P_+f])*(1.f/4096.f);
    float2 v=sP[ph*65+pw];
    sP[ph*65+pw]=make_float2(v.x*w,v.y*w);
  }
  __syncthreads();
  fft64_dir(sP,1,65,1.f,true);
  fft64_dir(sP,65,1,1.f,true);
  for(int idx=t;idx<4096;idx+=256){
    float2 v=sP[(idx>>6)*65+(idx&63)];
    re[idx]=v.x; im[idx]=v.y;
  }
}

__global__ __launch_bounds__(256) void k_haar(){
  int b=blockIdx.y;
  if(g_expert[b]!=2)return;
  int gid=blockIdx.x*256+threadIdx.x;
  int cp=gid>>11,q=gid&2047,h=q>>5,wp=q&31;
  size_t i0=(size_t)(b*256+2*cp)*P_+h*64+2*wp;
  float2 t0=*(const float2*)(g_xl+i0);
  float2 t1=*(const float2*)(g_xl+i0+P_);
  float sab=t0.x+t0.y,dab=t0.x-t0.y,scd=t1.x+t1.y,dcd=t1.x-t1.y;
  int pa=h*64+wp,pd=h*64+32+wp;
  float u00=(sab+scd)*0.25f*__ldg(&g_we[cp*P_+pa]);
  float u10=(sab-scd)*0.25f*__ldg(&g_we[(64+cp)*P_+pa]);
  float u01=(dab+dcd)*0.25f*__ldg(&g_we[cp*P_+pd]);
  float u11=(dab-dcd)*0.25f*__ldg(&g_we[(64+cp)*P_+pd]);
  float r0=u00+u01,r1=u00-u01,s0=u10+u11,s1=u10-u11;
  size_t o0=(size_t)(b*C_+2*cp)*P_+h*64+2*wp;
  *(float2*)(g_xo+o0)=make_float2(r0+s0,r1+s1);
  *(float2*)(g_xo+o0+P_)=make_float2(r0-s0,r1-s1);
}

__global__ __launch_bounds__(256) void k_lng(const float* __restrict__ og,
    const float* __restrict__ ob){
  int b=blockIdx.y,p=blockIdx.x*256+threadIdx.x;
  float s=0.f,s2=0.f;
  for(int c=0;c<128;c++){float v=g_xo[(size_t)(b*C_+c)*P_+p];s+=v;s2+=v*v;}
  float mu=s*(1.f/128.f);
  float rs=rsqrtf(fmaxf(s2*(1.f/128.f)-mu*mu,0.f)+1e-5f);
  for(int c=0;c<128;c++){
    float v=g_xo[(size_t)(b*C_+c)*P_+p];
    float z=g_xl[(size_t)(b*256+128+c)*P_+p];
    float sil=z/(1.f+expf(-z));
    g_xc[(size_t)(b*C_+c)*P_+p]=((v-mu)*rs*__ldg(og+c)+__ldg(ob+c))*sil;
  }
}

extern "C" void kernel_launch(void* const* d_in,const int* in_sizes,int n_in,
                              void* d_out,int out_size){
  const float* x=(const float*)d_in[0];
  const float* fe=(const float*)d_in[1];
  const float* dww=(const float*)d_in[2];
  const float* dwb=(const float*)d_in[3];
  const float* lw=(const float*)d_in[4];
  const float* lb=(const float*)d_in[5];
  const float* p1w=(const float*)d_in[6];
  const float* p1b=(const float*)d_in[7];
  const float* g1=(const float*)d_in[8];
  const float* b1=(const float*)d_in[9];
  const float* p2w=(const float*)d_in[10];
  const float* p2b=(const float*)d_in[11];
  const float* g2=(const float*)d_in[12];
  const float* b2=(const float*)d_in[13];
  const float* p3w=(const float*)d_in[14];
  const float* p3b=(const float*)d_in[15];
  const float* tw=(const float*)d_in[16];
  const float* tb=(const float*)d_in[17];
  const float* og=(const float*)d_in[18];
  const float* ob=(const float*)d_in[19];
  const float* olw=(const float*)d_in[20];
  const float* olb=(const float*)d_in[21];
  const float* gum=(const float*)d_in[22];
  float* out=(float*)d_out;
  float *gxc,*gxl,*gxo,*gca,*gwcf,*gwci;
  cudaGetSymbolAddress((void**)&gxc,g_xc);
  cudaGetSymbolAddress((void**)&gxl,g_xl);
  cudaGetSymbolAddress((void**)&gxo,g_xo);
  cudaGetSymbolAddress((void**)&gca,g_cA);
  cudaGetSymbolAddress((void**)&gwcf,g_WCf);
  cudaGetSymbolAddress((void**)&gwci,g_WCi);

  static cudaStream_t s1=0,s2=0;
  static cudaEvent_t ev0=0,evA=0,evB=0,evC=0,evD=0;
  if(!s1){
    cudaStreamCreateWithFlags(&s1,cudaStreamNonBlocking);
    cudaStreamCreateWithFlags(&s2,cudaStreamNonBlocking);
    cudaEventCreateWithFlags(&ev0,cudaEventDisableTiming);
    cudaEventCreateWithFlags(&evA,cudaEventDisableTiming);
    cudaEventCreateWithFlags(&evB,cudaEventDisableTiming);
    cudaEventCreateWithFlags(&evC,cudaEventDisableTiming);
    cudaEventCreateWithFlags(&evD,cudaEventDisableTiming);
  }

  // fork: consts + we on s1, main chain on default stream
  cudaEventRecord(ev0,0);
  cudaStreamWaitEvent(s1,ev0,0);
  k_consts<<<64,256,0,s1>>>();
  k_we<<<128,256,0,s1>>>(fe,tw,tb);
  cudaEventRecord(evA,s1);

  k_conv<<<dim3(16,128,32),256>>>(x,dww,dwb);
  k_gemm<<<dim3(64,4,32),256>>>(gxc,(size_t)128*P_,128,lw,lb,gxl,(size_t)256*P_,-1);
  k_mean<<<dim3(128,32),128>>>();
  k_router<<<1,256>>>(p1w,p1b,g1,b1,p2w,p2b,g2,b2,p3w,p3b,gum);

  cudaStreamWaitEvent(0,evA,0);   // experts need g_we / g_wn / WCf
  cudaEventRecord(evB,0);
  cudaStreamWaitEvent(s1,evB,0);
  cudaStreamWaitEvent(s2,evB,0);

  k_dct<<<dim3(128,32),256,0,s1>>>();
  cudaEventRecord(evC,s1);
  k_haar<<<dim3(512,32),256,0,s2>>>();
  cudaEventRecord(evD,s2);

  k_gemm<<<dim3(64,4,32),256>>>(gxl,(size_t)256*P_,128,gwcf,(const float*)0,gca,(size_t)256*P_,1);
  k_pfft<<<dim3(128,32),256>>>();
  k_gemm<<<dim3(64,2,32),256>>>(gca,(size_t)256*P_,256,gwci,(const float*)0,gxo,(size_t)128*P_,1);

  cudaStreamWaitEvent(0,evC,0);
  cudaStreamWaitEvent(0,evD,0);

  k_lng<<<dim3(16,32),256>>>(og,ob);
  k_gemm<<<dim3(64,2,32),256>>>(gxc,(size_t)128*P_,128,olw,olb,out,(size_t)128*P_,-1);
}